// round 1
// baseline (speedup 1.0000x reference)
#include <cuda_runtime.h>
#include <math.h>

// Problem constants
#define B_   4
#define T_   2048
#define D_   1024
#define H_   16
#define DH_  64
#define NTOK (B_ * T_)     // 8192
#define E3   (3 * D_)      // 3072

// Scratch (device globals: allocation-free rule)
__device__ __align__(16) float g_qkv[NTOK * E3];   // [8192, 3072]
__device__ __align__(16) float g_att[NTOK * D_];   // [8192, 1024]

// ---------------------------------------------------------------------------
// NT SGEMM: C[m,n] = sum_k A[m*K+k] * Bm[n*K+k]
// BM=BN=64, BK=16, 256 threads, 4x4 register micro-tile.
// ---------------------------------------------------------------------------
__global__ void __launch_bounds__(256, 4)
gemm_nt_kernel(const float* __restrict__ A, const float* __restrict__ Bm,
               float* __restrict__ C, int M, int N, int K)
{
    __shared__ float As[16][68];   // [k][m], padded
    __shared__ float Bs[16][68];   // [k][n], padded

    const int tid = threadIdx.x;
    const int ty  = tid >> 4;      // 0..15
    const int tx  = tid & 15;      // 0..15
    const int m0  = blockIdx.y * 64;
    const int n0  = blockIdx.x * 64;

    const int lrow = tid >> 2;          // 0..63
    const int lk4  = (tid & 3) << 2;    // 0,4,8,12

    float acc[4][4] = {};

    for (int k0 = 0; k0 < K; k0 += 16) {
        float4 av = *(const float4*)&A[(size_t)(m0 + lrow) * K + k0 + lk4];
        float4 bv = *(const float4*)&Bm[(size_t)(n0 + lrow) * K + k0 + lk4];
        As[lk4 + 0][lrow] = av.x;
        As[lk4 + 1][lrow] = av.y;
        As[lk4 + 2][lrow] = av.z;
        As[lk4 + 3][lrow] = av.w;
        Bs[lk4 + 0][lrow] = bv.x;
        Bs[lk4 + 1][lrow] = bv.y;
        Bs[lk4 + 2][lrow] = bv.z;
        Bs[lk4 + 3][lrow] = bv.w;
        __syncthreads();

        #pragma unroll
        for (int k = 0; k < 16; ++k) {
            float4 a4 = *(const float4*)&As[k][ty << 2];
            float4 b4 = *(const float4*)&Bs[k][tx << 2];
            acc[0][0] += a4.x * b4.x; acc[0][1] += a4.x * b4.y;
            acc[0][2] += a4.x * b4.z; acc[0][3] += a4.x * b4.w;
            acc[1][0] += a4.y * b4.x; acc[1][1] += a4.y * b4.y;
            acc[1][2] += a4.y * b4.z; acc[1][3] += a4.y * b4.w;
            acc[2][0] += a4.z * b4.x; acc[2][1] += a4.z * b4.y;
            acc[2][2] += a4.z * b4.z; acc[2][3] += a4.z * b4.w;
            acc[3][0] += a4.w * b4.x; acc[3][1] += a4.w * b4.y;
            acc[3][2] += a4.w * b4.z; acc[3][3] += a4.w * b4.w;
        }
        __syncthreads();
    }

    #pragma unroll
    for (int i = 0; i < 4; ++i) {
        float4 r = make_float4(acc[i][0], acc[i][1], acc[i][2], acc[i][3]);
        *(float4*)&C[(size_t)(m0 + (ty << 2) + i) * N + n0 + (tx << 2)] = r;
    }
}

// ---------------------------------------------------------------------------
// Flash attention (fp32 online softmax), BLOCK_M = BLOCK_N = 64, DH = 64.
// Grid: (T/64, H, B), 256 threads. Dynamic smem:
//   QsT[64][68] (d-major), KsT[64][68] (d-major), Vs[64][68] (key-major),
//   Ss[64][68], m[64], l[64], corr[64]  -> 70400 bytes
// ---------------------------------------------------------------------------
#define ATTN_SMEM_BYTES ((4 * 64 * 68 + 3 * 64) * 4)

__global__ void __launch_bounds__(256, 1)
attn_kernel(const float* __restrict__ qkv, float* __restrict__ out)
{
    extern __shared__ float sm[];
    float* QsT = sm;                 // [d][row] stride 68
    float* KsT = QsT + 64 * 68;      // [d][row] stride 68
    float* Vs  = KsT + 64 * 68;      // [key][d] stride 68
    float* Ss  = Vs  + 64 * 68;      // [row][key] stride 68
    float* m_s = Ss  + 64 * 68;
    float* l_s = m_s + 64;
    float* c_s = l_s + 64;

    const int tid = threadIdx.x;
    const int ty  = tid >> 4;        // 0..15
    const int tx  = tid & 15;        // 0..15
    const int qt  = blockIdx.x;      // query tile 0..31
    const int h   = blockIdx.y;
    const int b   = blockIdx.z;

    const float scale = 0.125f;      // 1/sqrt(64)

    // Load Q tile (pre-scaled), stored d-major
    #pragma unroll
    for (int w = 0; w < 4; ++w) {
        int f   = tid + w * 256;
        int row = f >> 4;
        int c4  = (f & 15) << 2;
        const float* p = qkv + (size_t)(b * T_ + qt * 64 + row) * E3 + h * DH_ + c4;
        float4 v = *(const float4*)p;
        QsT[(c4 + 0) * 68 + row] = v.x * scale;
        QsT[(c4 + 1) * 68 + row] = v.y * scale;
        QsT[(c4 + 2) * 68 + row] = v.z * scale;
        QsT[(c4 + 3) * 68 + row] = v.w * scale;
    }
    if (tid < 64) { m_s[tid] = -3.0e38f; l_s[tid] = 0.0f; }

    float acc[4][4] = {};

    for (int n = 0; n <= qt; ++n) {
        __syncthreads();  // prev PV / Q-load done before overwriting K,V

        // Load K (d-major) and V (key-major) tiles
        #pragma unroll
        for (int w = 0; w < 4; ++w) {
            int f   = tid + w * 256;
            int row = f >> 4;
            int c4  = (f & 15) << 2;
            const float* kp = qkv + (size_t)(b * T_ + n * 64 + row) * E3 + D_ + h * DH_ + c4;
            const float* vp = kp + D_;
            float4 kv = *(const float4*)kp;
            float4 vv = *(const float4*)vp;
            KsT[(c4 + 0) * 68 + row] = kv.x;
            KsT[(c4 + 1) * 68 + row] = kv.y;
            KsT[(c4 + 2) * 68 + row] = kv.z;
            KsT[(c4 + 3) * 68 + row] = kv.w;
            *(float4*)&Vs[row * 68 + c4] = vv;
        }
        __syncthreads();

        // S = (Q*scale) @ K^T  (4x4 per thread)
        float s_acc[4][4] = {};
        #pragma unroll 16
        for (int d = 0; d < 64; ++d) {
            float4 a4 = *(const float4*)&QsT[d * 68 + (ty << 2)];
            float4 b4 = *(const float4*)&KsT[d * 68 + (tx << 2)];
            s_acc[0][0] += a4.x * b4.x; s_acc[0][1] += a4.x * b4.y;
            s_acc[0][2] += a4.x * b4.z; s_acc[0][3] += a4.x * b4.w;
            s_acc[1][0] += a4.y * b4.x; s_acc[1][1] += a4.y * b4.y;
            s_acc[1][2] += a4.y * b4.z; s_acc[1][3] += a4.y * b4.w;
            s_acc[2][0] += a4.z * b4.x; s_acc[2][1] += a4.z * b4.y;
            s_acc[2][2] += a4.z * b4.z; s_acc[2][3] += a4.z * b4.w;
            s_acc[3][0] += a4.w * b4.x; s_acc[3][1] += a4.w * b4.y;
            s_acc[3][2] += a4.w * b4.z; s_acc[3][3] += a4.w * b4.w;
        }

        const bool diag = (n == qt);
        #pragma unroll
        for (int i = 0; i < 4; ++i) {
            int il = (ty << 2) + i;
            float4 r;
            float* rr = &r.x;
            #pragma unroll
            for (int j = 0; j < 4; ++j) {
                int jl = (tx << 2) + j;
                float sv = s_acc[i][j];
                if (diag && il < jl) sv = -3.0e38f;
                rr[j] = sv;
            }
            *(float4*)&Ss[il * 68 + (tx << 2)] = r;
        }
        __syncthreads();

        // Online softmax row pass (one thread per row)
        if (tid < 64) {
            int r = tid;
            float mold = m_s[r];
            float mx = mold;
            #pragma unroll 8
            for (int j = 0; j < 64; ++j) mx = fmaxf(mx, Ss[r * 68 + j]);
            float corr = __expf(mold - mx);
            float sum = 0.0f;
            #pragma unroll 8
            for (int j = 0; j < 64; ++j) {
                float p = __expf(Ss[r * 68 + j] - mx);
                Ss[r * 68 + j] = p;
                sum += p;
            }
            l_s[r] = l_s[r] * corr + sum;
            m_s[r] = mx;
            c_s[r] = corr;
        }
        __syncthreads();

        // Rescale accumulators, then O += P @ V
        float cr[4];
        #pragma unroll
        for (int i = 0; i < 4; ++i) cr[i] = c_s[(ty << 2) + i];
        #pragma unroll
        for (int i = 0; i < 4; ++i)
            #pragma unroll
            for (int j = 0; j < 4; ++j) acc[i][j] *= cr[i];

        #pragma unroll 8
        for (int jj = 0; jj < 64; ++jj) {
            float4 v4 = *(const float4*)&Vs[jj * 68 + (tx << 2)];
            float s0 = Ss[((ty << 2) + 0) * 68 + jj];
            float s1 = Ss[((ty << 2) + 1) * 68 + jj];
            float s2 = Ss[((ty << 2) + 2) * 68 + jj];
            float s3 = Ss[((ty << 2) + 3) * 68 + jj];
            acc[0][0] += s0 * v4.x; acc[0][1] += s0 * v4.y;
            acc[0][2] += s0 * v4.z; acc[0][3] += s0 * v4.w;
            acc[1][0] += s1 * v4.x; acc[1][1] += s1 * v4.y;
            acc[1][2] += s1 * v4.z; acc[1][3] += s1 * v4.w;
            acc[2][0] += s2 * v4.x; acc[2][1] += s2 * v4.y;
            acc[2][2] += s2 * v4.z; acc[2][3] += s2 * v4.w;
            acc[3][0] += s3 * v4.x; acc[3][1] += s3 * v4.y;
            acc[3][2] += s3 * v4.z; acc[3][3] += s3 * v4.w;
        }
    }

    // Epilogue: normalize and store to [B,T,H*DH] layout
    #pragma unroll
    for (int i = 0; i < 4; ++i) {
        float linv = 1.0f / l_s[(ty << 2) + i];
        float4 r = make_float4(acc[i][0] * linv, acc[i][1] * linv,
                               acc[i][2] * linv, acc[i][3] * linv);
        int t = qt * 64 + (ty << 2) + i;
        *(float4*)&out[(size_t)(b * T_ + t) * D_ + h * DH_ + (tx << 2)] = r;
    }
}

// ---------------------------------------------------------------------------
extern "C" void kernel_launch(void* const* d_in, const int* in_sizes, int n_in,
                              void* d_out, int out_size)
{
    const float* x      = (const float*)d_in[0];
    const float* w_attn = (const float*)d_in[1];
    const float* w_proj = (const float*)d_in[2];
    float* out = (float*)d_out;

    float *qkv, *att;
    cudaGetSymbolAddress((void**)&qkv, g_qkv);
    cudaGetSymbolAddress((void**)&att, g_att);

    // 1) QKV projection: [8192,1024] x [3072,1024]^T -> [8192,3072]
    {
        dim3 grid(E3 / 64, NTOK / 64);
        gemm_nt_kernel<<<grid, 256>>>(x, w_attn, qkv, NTOK, E3, D_);
    }

    // 2) Causal flash attention -> g_att [8192,1024]
    {
        cudaFuncSetAttribute(attn_kernel,
                             cudaFuncAttributeMaxDynamicSharedMemorySize,
                             ATTN_SMEM_BYTES);
        dim3 grid(T_ / 64, H_, B_);
        attn_kernel<<<grid, 256, ATTN_SMEM_BYTES>>>(qkv, att);
    }

    // 3) Output projection: [8192,1024] x [1024,1024]^T -> [8192,1024]
    {
        dim3 grid(D_ / 64, NTOK / 64);
        gemm_nt_kernel<<<grid, 256>>>(att, w_proj, out, NTOK, D_, D_);
    }
}

// round 2
// speedup vs baseline: 1.7283x; 1.7283x over previous
#include <cuda_runtime.h>
#include <math.h>
#include <stdint.h>

// Problem constants
#define B_   4
#define T_   2048
#define D_   1024
#define H_   16
#define DH_  64
#define NTOK (B_ * T_)     // 8192
#define E3   (3 * D_)      // 3072

// Scratch (device globals: allocation-free rule)
__device__ __align__(16) float g_qkv[NTOK * E3];   // [8192, 3072]
__device__ __align__(16) float g_att[NTOK * D_];   // [8192, 1024]

// ---------------------------------------------------------------------------
// TF32 tensor-core NT GEMM: C[m,n] = sum_k A[m*K+k] * Bm[n*K+k]
// BM=BN=128, BK=16, 256 threads (8 warps), warp tile 64x32 via mma.m16n8k8.
// smem tiles stored [row][k] with row stride 20 floats (conflict-free frags).
// ---------------------------------------------------------------------------
#define BM 128
#define BN 128
#define BK 16
#define TSTR 20   // smem row stride in 32-bit words

__device__ __forceinline__ uint32_t f2tf32(float x) {
    uint32_t r;
    asm("cvt.rna.tf32.f32 %0, %1;" : "=r"(r) : "f"(x));
    return r;
}

__device__ __forceinline__ void mma_tf32(float* c, const uint32_t* a, const uint32_t* b) {
    asm volatile(
        "mma.sync.aligned.m16n8k8.row.col.f32.tf32.tf32.f32 "
        "{%0,%1,%2,%3}, {%4,%5,%6,%7}, {%8,%9}, {%0,%1,%2,%3};\n"
        : "+f"(c[0]), "+f"(c[1]), "+f"(c[2]), "+f"(c[3])
        : "r"(a[0]), "r"(a[1]), "r"(a[2]), "r"(a[3]), "r"(b[0]), "r"(b[1]));
}

__global__ void __launch_bounds__(256, 2)
gemm_nt_tf32(const float* __restrict__ A, const float* __restrict__ Bm,
             float* __restrict__ C, int M, int N, int K)
{
    __shared__ uint32_t As[BM * TSTR];
    __shared__ uint32_t Bs[BN * TSTR];

    const int tid  = threadIdx.x;
    const int lane = tid & 31;
    const int warp = tid >> 5;
    const int wm   = (warp >> 2) * 64;  // 0 or 64
    const int wn   = (warp & 3) * 32;   // 0,32,64,96
    const int m0   = blockIdx.y * BM;
    const int n0   = blockIdx.x * BN;

    const int lrow = tid >> 2;          // 0..63
    const int lk   = (tid & 3) << 2;    // 0,4,8,12

    const float* aP0 = A  + (size_t)(m0 + lrow) * K + lk;
    const float* aP1 = aP0 + (size_t)64 * K;
    const float* bP0 = Bm + (size_t)(n0 + lrow) * K + lk;
    const float* bP1 = bP0 + (size_t)64 * K;

    float acc[4][4][4] = {};

    for (int k0 = 0; k0 < K; k0 += BK) {
        float4 av0 = *(const float4*)(aP0 + k0);
        float4 av1 = *(const float4*)(aP1 + k0);
        float4 bv0 = *(const float4*)(bP0 + k0);
        float4 bv1 = *(const float4*)(bP1 + k0);

        __syncthreads();   // previous compute done before overwrite

        uint4 at0 = make_uint4(f2tf32(av0.x), f2tf32(av0.y), f2tf32(av0.z), f2tf32(av0.w));
        uint4 at1 = make_uint4(f2tf32(av1.x), f2tf32(av1.y), f2tf32(av1.z), f2tf32(av1.w));
        uint4 bt0 = make_uint4(f2tf32(bv0.x), f2tf32(bv0.y), f2tf32(bv0.z), f2tf32(bv0.w));
        uint4 bt1 = make_uint4(f2tf32(bv1.x), f2tf32(bv1.y), f2tf32(bv1.z), f2tf32(bv1.w));

        *(uint4*)&As[lrow * TSTR + lk]        = at0;
        *(uint4*)&As[(lrow + 64) * TSTR + lk] = at1;
        *(uint4*)&Bs[lrow * TSTR + lk]        = bt0;
        *(uint4*)&Bs[(lrow + 64) * TSTR + lk] = bt1;

        __syncthreads();

        #pragma unroll
        for (int ks = 0; ks < BK; ks += 8) {
            uint32_t af[4][4], bf[4][2];
            const int kk = ks + (lane & 3);
            #pragma unroll
            for (int mi = 0; mi < 4; ++mi) {
                int row = wm + mi * 16 + (lane >> 2);
                af[mi][0] = As[row * TSTR + kk];
                af[mi][1] = As[(row + 8) * TSTR + kk];
                af[mi][2] = As[row * TSTR + kk + 4];
                af[mi][3] = As[(row + 8) * TSTR + kk + 4];
            }
            #pragma unroll
            for (int nj = 0; nj < 4; ++nj) {
                int col = wn + nj * 8 + (lane >> 2);
                bf[nj][0] = Bs[col * TSTR + kk];
                bf[nj][1] = Bs[col * TSTR + kk + 4];
            }
            #pragma unroll
            for (int mi = 0; mi < 4; ++mi)
                #pragma unroll
                for (int nj = 0; nj < 4; ++nj)
                    mma_tf32(acc[mi][nj], af[mi], bf[nj]);
        }
    }

    // Epilogue
    #pragma unroll
    for (int mi = 0; mi < 4; ++mi) {
        int row = m0 + wm + mi * 16 + (lane >> 2);
        #pragma unroll
        for (int nj = 0; nj < 4; ++nj) {
            int col = n0 + wn + nj * 8 + ((lane & 3) << 1);
            *(float2*)&C[(size_t)row * N + col] =
                make_float2(acc[mi][nj][0], acc[mi][nj][1]);
            *(float2*)&C[(size_t)(row + 8) * N + col] =
                make_float2(acc[mi][nj][2], acc[mi][nj][3]);
        }
    }
}

// ---------------------------------------------------------------------------
// Flash attention (fp32 online softmax), BLOCK_M = BLOCK_N = 64, DH = 64.
// ---------------------------------------------------------------------------
#define ATTN_SMEM_BYTES ((4 * 64 * 68 + 3 * 64) * 4)

__global__ void __launch_bounds__(256, 1)
attn_kernel(const float* __restrict__ qkv, float* __restrict__ out)
{
    extern __shared__ float sm[];
    float* QsT = sm;                 // [d][row] stride 68
    float* KsT = QsT + 64 * 68;      // [d][row] stride 68
    float* Vs  = KsT + 64 * 68;      // [key][d] stride 68
    float* Ss  = Vs  + 64 * 68;      // [row][key] stride 68
    float* m_s = Ss  + 64 * 68;
    float* l_s = m_s + 64;
    float* c_s = l_s + 64;

    const int tid = threadIdx.x;
    const int ty  = tid >> 4;
    const int tx  = tid & 15;
    const int qt  = blockIdx.x;
    const int h   = blockIdx.y;
    const int b   = blockIdx.z;

    const float scale = 0.125f;

    #pragma unroll
    for (int w = 0; w < 4; ++w) {
        int f   = tid + w * 256;
        int row = f >> 4;
        int c4  = (f & 15) << 2;
        const float* p = qkv + (size_t)(b * T_ + qt * 64 + row) * E3 + h * DH_ + c4;
        float4 v = *(const float4*)p;
        QsT[(c4 + 0) * 68 + row] = v.x * scale;
        QsT[(c4 + 1) * 68 + row] = v.y * scale;
        QsT[(c4 + 2) * 68 + row] = v.z * scale;
        QsT[(c4 + 3) * 68 + row] = v.w * scale;
    }
    if (tid < 64) { m_s[tid] = -3.0e38f; l_s[tid] = 0.0f; }

    float acc[4][4] = {};

    for (int n = 0; n <= qt; ++n) {
        __syncthreads();

        #pragma unroll
        for (int w = 0; w < 4; ++w) {
            int f   = tid + w * 256;
            int row = f >> 4;
            int c4  = (f & 15) << 2;
            const float* kp = qkv + (size_t)(b * T_ + n * 64 + row) * E3 + D_ + h * DH_ + c4;
            const float* vp = kp + D_;
            float4 kv = *(const float4*)kp;
            float4 vv = *(const float4*)vp;
            KsT[(c4 + 0) * 68 + row] = kv.x;
            KsT[(c4 + 1) * 68 + row] = kv.y;
            KsT[(c4 + 2) * 68 + row] = kv.z;
            KsT[(c4 + 3) * 68 + row] = kv.w;
            *(float4*)&Vs[row * 68 + c4] = vv;
        }
        __syncthreads();

        float s_acc[4][4] = {};
        #pragma unroll 16
        for (int d = 0; d < 64; ++d) {
            float4 a4 = *(const float4*)&QsT[d * 68 + (ty << 2)];
            float4 b4 = *(const float4*)&KsT[d * 68 + (tx << 2)];
            s_acc[0][0] += a4.x * b4.x; s_acc[0][1] += a4.x * b4.y;
            s_acc[0][2] += a4.x * b4.z; s_acc[0][3] += a4.x * b4.w;
            s_acc[1][0] += a4.y * b4.x; s_acc[1][1] += a4.y * b4.y;
            s_acc[1][2] += a4.y * b4.z; s_acc[1][3] += a4.y * b4.w;
            s_acc[2][0] += a4.z * b4.x; s_acc[2][1] += a4.z * b4.y;
            s_acc[2][2] += a4.z * b4.z; s_acc[2][3] += a4.z * b4.w;
            s_acc[3][0] += a4.w * b4.x; s_acc[3][1] += a4.w * b4.y;
            s_acc[3][2] += a4.w * b4.z; s_acc[3][3] += a4.w * b4.w;
        }

        const bool diag = (n == qt);
        #pragma unroll
        for (int i = 0; i < 4; ++i) {
            int il = (ty << 2) + i;
            float4 r;
            float* rr = &r.x;
            #pragma unroll
            for (int j = 0; j < 4; ++j) {
                int jl = (tx << 2) + j;
                float sv = s_acc[i][j];
                if (diag && il < jl) sv = -3.0e38f;
                rr[j] = sv;
            }
            *(float4*)&Ss[il * 68 + (tx << 2)] = r;
        }
        __syncthreads();

        if (tid < 64) {
            int r = tid;
            float mold = m_s[r];
            float mx = mold;
            #pragma unroll 8
            for (int j = 0; j < 64; ++j) mx = fmaxf(mx, Ss[r * 68 + j]);
            float corr = __expf(mold - mx);
            float sum = 0.0f;
            #pragma unroll 8
            for (int j = 0; j < 64; ++j) {
                float p = __expf(Ss[r * 68 + j] - mx);
                Ss[r * 68 + j] = p;
                sum += p;
            }
            l_s[r] = l_s[r] * corr + sum;
            m_s[r] = mx;
            c_s[r] = corr;
        }
        __syncthreads();

        float cr[4];
        #pragma unroll
        for (int i = 0; i < 4; ++i) cr[i] = c_s[(ty << 2) + i];
        #pragma unroll
        for (int i = 0; i < 4; ++i)
            #pragma unroll
            for (int j = 0; j < 4; ++j) acc[i][j] *= cr[i];

        #pragma unroll 8
        for (int jj = 0; jj < 64; ++jj) {
            float4 v4 = *(const float4*)&Vs[jj * 68 + (tx << 2)];
            float s0 = Ss[((ty << 2) + 0) * 68 + jj];
            float s1 = Ss[((ty << 2) + 1) * 68 + jj];
            float s2 = Ss[((ty << 2) + 2) * 68 + jj];
            float s3 = Ss[((ty << 2) + 3) * 68 + jj];
            acc[0][0] += s0 * v4.x; acc[0][1] += s0 * v4.y;
            acc[0][2] += s0 * v4.z; acc[0][3] += s0 * v4.w;
            acc[1][0] += s1 * v4.x; acc[1][1] += s1 * v4.y;
            acc[1][2] += s1 * v4.z; acc[1][3] += s1 * v4.w;
            acc[2][0] += s2 * v4.x; acc[2][1] += s2 * v4.y;
            acc[2][2] += s2 * v4.z; acc[2][3] += s2 * v4.w;
            acc[3][0] += s3 * v4.x; acc[3][1] += s3 * v4.y;
            acc[3][2] += s3 * v4.z; acc[3][3] += s3 * v4.w;
        }
    }

    #pragma unroll
    for (int i = 0; i < 4; ++i) {
        float linv = 1.0f / l_s[(ty << 2) + i];
        float4 r = make_float4(acc[i][0] * linv, acc[i][1] * linv,
                               acc[i][2] * linv, acc[i][3] * linv);
        int t = qt * 64 + (ty << 2) + i;
        *(float4*)&out[(size_t)(b * T_ + t) * D_ + h * DH_ + (tx << 2)] = r;
    }
}

// ---------------------------------------------------------------------------
extern "C" void kernel_launch(void* const* d_in, const int* in_sizes, int n_in,
                              void* d_out, int out_size)
{
    const float* x      = (const float*)d_in[0];
    const float* w_attn = (const float*)d_in[1];
    const float* w_proj = (const float*)d_in[2];
    float* out = (float*)d_out;

    float *qkv, *att;
    cudaGetSymbolAddress((void**)&qkv, g_qkv);
    cudaGetSymbolAddress((void**)&att, g_att);

    // 1) QKV projection: [8192,1024] x [3072,1024]^T -> [8192,3072]  (TF32 mma)
    {
        dim3 grid(E3 / BN, NTOK / BM);
        gemm_nt_tf32<<<grid, 256>>>(x, w_attn, qkv, NTOK, E3, D_);
    }

    // 2) Causal flash attention -> g_att [8192,1024]  (fp32)
    {
        cudaFuncSetAttribute(attn_kernel,
                             cudaFuncAttributeMaxDynamicSharedMemorySize,
                             ATTN_SMEM_BYTES);
        dim3 grid(T_ / 64, H_, B_);
        attn_kernel<<<grid, 256, ATTN_SMEM_BYTES>>>(qkv, att);
    }

    // 3) Output projection: [8192,1024] x [1024,1024]^T -> [8192,1024]  (TF32 mma)
    {
        dim3 grid(D_ / BN, NTOK / BM);
        gemm_nt_tf32<<<grid, 256>>>(att, w_proj, out, NTOK, D_, D_);
    }
}

// round 3
// speedup vs baseline: 2.6794x; 1.5503x over previous
#include <cuda_runtime.h>
#include <math.h>
#include <stdint.h>

// Problem constants
#define B_   4
#define T_   2048
#define D_   1024
#define H_   16
#define DH_  64
#define NTOK (B_ * T_)     // 8192
#define E3   (3 * D_)      // 3072

// Scratch (device globals: allocation-free rule)
__device__ __align__(16) float g_qkv[NTOK * E3];   // [8192, 3072]
__device__ __align__(16) float g_att[NTOK * D_];   // [8192, 1024]
__device__ __align__(16) float g_xr [NTOK * D_];   // tf32-rounded x
__device__ __align__(16) float g_war[E3 * D_];     // tf32-rounded w_attn
__device__ __align__(16) float g_wpr[D_ * D_];     // tf32-rounded w_proj

// ---------------------------------------------------------------------------
// Helpers
// ---------------------------------------------------------------------------
__device__ __forceinline__ float tf32r(float x) {
    uint32_t u;
    asm("cvt.rna.tf32.f32 %0, %1;" : "=r"(u) : "f"(x));
    return __uint_as_float(u);
}

__device__ __forceinline__ void mma_tf32(float* c, const float* a, float b0, float b1) {
    asm volatile(
        "mma.sync.aligned.m16n8k8.row.col.f32.tf32.tf32.f32 "
        "{%0,%1,%2,%3}, {%4,%5,%6,%7}, {%8,%9}, {%0,%1,%2,%3};\n"
        : "+f"(c[0]), "+f"(c[1]), "+f"(c[2]), "+f"(c[3])
        : "r"(__float_as_uint(a[0])), "r"(__float_as_uint(a[1])),
          "r"(__float_as_uint(a[2])), "r"(__float_as_uint(a[3])),
          "r"(__float_as_uint(b0)), "r"(__float_as_uint(b1)));
}

__device__ __forceinline__ void cp_async16(void* smem_dst, const void* gsrc) {
    uint32_t s = (uint32_t)__cvta_generic_to_shared(smem_dst);
    asm volatile("cp.async.cg.shared.global [%0], [%1], 16;\n" :: "r"(s), "l"(gsrc) : "memory");
}
__device__ __forceinline__ void cp_commit() {
    asm volatile("cp.async.commit_group;\n" ::: "memory");
}
template<int N>
__device__ __forceinline__ void cp_wait() {
    asm volatile("cp.async.wait_group %0;\n" :: "n"(N) : "memory");
}

// ---------------------------------------------------------------------------
// Pre-round to tf32 (rna), elementwise
// ---------------------------------------------------------------------------
__global__ void round_tf32_kernel(const float4* __restrict__ in,
                                  float4* __restrict__ out, int n4)
{
    int i = blockIdx.x * blockDim.x + threadIdx.x;
    if (i < n4) {
        float4 v = in[i];
        v.x = tf32r(v.x); v.y = tf32r(v.y); v.z = tf32r(v.z); v.w = tf32r(v.w);
        out[i] = v;
    }
}

// ---------------------------------------------------------------------------
// TF32 NT GEMM, inputs pre-rounded to tf32. BM=BN=128, BK=16, 3-stage cp.async.
// 256 threads (8 warps), warp tile 64x32.
// ---------------------------------------------------------------------------
#define BM 128
#define BN 128
#define BK 16
#define TSTR 20
#define GEMM_STAGE_WORDS (BM * TSTR)         // 2560 words per tile
#define GEMM_SMEM_BYTES (3 * 2 * GEMM_STAGE_WORDS * 4)  // 61440

__global__ void __launch_bounds__(256, 2)
gemm_nt_tf32(const float* __restrict__ A, const float* __restrict__ Bm,
             float* __restrict__ C, int M, int N, int K)
{
    extern __shared__ float smg[];
    // stage s: A at smg + s*2*SW, B at + SW
    const int SW = GEMM_STAGE_WORDS;

    const int tid  = threadIdx.x;
    const int lane = tid & 31;
    const int warp = tid >> 5;
    const int wm   = (warp >> 2) * 64;
    const int wn   = (warp & 3) * 32;
    const int m0   = blockIdx.y * BM;
    const int n0   = blockIdx.x * BN;

    float acc[4][4][4] = {};

    const int nIter = K / BK;

    auto issue = [&](int it, int s) {
        float* As = smg + s * 2 * SW;
        float* Bs = As + SW;
        int k0 = it * BK;
        #pragma unroll
        for (int i = 0; i < 2; ++i) {
            int c   = tid + i * 256;
            int row = c >> 2;
            int lk  = (c & 3) << 2;
            cp_async16(&As[row * TSTR + lk], &A[(size_t)(m0 + row) * K + k0 + lk]);
            cp_async16(&Bs[row * TSTR + lk], &Bm[(size_t)(n0 + row) * K + k0 + lk]);
        }
        cp_commit();
    };

    issue(0, 0);
    issue(1, 1);

    for (int it = 0; it < nIter; ++it) {
        int s = it % 3;
        cp_wait<1>();
        __syncthreads();
        if (it + 2 < nIter) issue(it + 2, (it + 2) % 3);
        else cp_commit();   // keep group accounting uniform

        const float* As = smg + s * 2 * SW;
        const float* Bs = As + SW;

        #pragma unroll
        for (int ks = 0; ks < BK; ks += 8) {
            float af[4][4], bf[4][2];
            const int kk = ks + (lane & 3);
            #pragma unroll
            for (int mi = 0; mi < 4; ++mi) {
                int row = wm + mi * 16 + (lane >> 2);
                af[mi][0] = As[row * TSTR + kk];
                af[mi][1] = As[(row + 8) * TSTR + kk];
                af[mi][2] = As[row * TSTR + kk + 4];
                af[mi][3] = As[(row + 8) * TSTR + kk + 4];
            }
            #pragma unroll
            for (int nj = 0; nj < 4; ++nj) {
                int col = wn + nj * 8 + (lane >> 2);
                bf[nj][0] = Bs[col * TSTR + kk];
                bf[nj][1] = Bs[col * TSTR + kk + 4];
            }
            #pragma unroll
            for (int mi = 0; mi < 4; ++mi)
                #pragma unroll
                for (int nj = 0; nj < 4; ++nj)
                    mma_tf32(acc[mi][nj], af[mi], bf[nj][0], bf[nj][1]);
        }
        __syncthreads();
    }

    #pragma unroll
    for (int mi = 0; mi < 4; ++mi) {
        int row = m0 + wm + mi * 16 + (lane >> 2);
        #pragma unroll
        for (int nj = 0; nj < 4; ++nj) {
            int col = n0 + wn + nj * 8 + ((lane & 3) << 1);
            *(float2*)&C[(size_t)row * N + col] =
                make_float2(acc[mi][nj][0], acc[mi][nj][1]);
            *(float2*)&C[(size_t)(row + 8) * N + col] =
                make_float2(acc[mi][nj][2], acc[mi][nj][3]);
        }
    }
}

// ---------------------------------------------------------------------------
// Flash attention on tensor cores (tf32 mma, 3x-split for S, fp32 softmax).
// BLOCK_M=64 q rows, key tiles of 64, DH=64. 128 threads (4 warps),
// each warp owns 16 q rows. S-frags + O-acc in registers.
// ---------------------------------------------------------------------------
#define AT_STR 68
#define ATTN_SMEM_BYTES (6 * 64 * AT_STR * 4)   // 104448

__global__ void __launch_bounds__(128, 2)
attn_mma_kernel(const float* __restrict__ qkv, float* __restrict__ out)
{
    extern __shared__ float sm[];
    float* Qb = sm;                  // [row][d]  big
    float* Qs = Qb + 64 * AT_STR;    // [row][d]  small
    float* Kb = Qs + 64 * AT_STR;    // [key][d]  big
    float* Ks = Kb + 64 * AT_STR;    // [key][d]  small
    float* Vt = Ks + 64 * AT_STR;    // [d][key]  (rna)
    float* Ps = Vt + 64 * AT_STR;    // [row][key] (rna)

    const int tid  = threadIdx.x;
    const int lane = tid & 31;
    const int warp = tid >> 5;
    const int g    = lane >> 2;      // 0..7
    const int t    = lane & 3;       // 0..3
    const int m0   = warp * 16;
    const int qt   = gridDim.x - 1 - blockIdx.x;   // big tiles first
    const int h    = blockIdx.y;
    const int b    = blockIdx.z;

    const float scale = 0.125f;
    const float* qbase = qkv + (size_t)(b * T_ + qt * 64) * E3 + h * DH_;

    // Load Q, pre-scale, split big/small
    #pragma unroll
    for (int i = 0; i < 8; ++i) {
        int f = tid + i * 128;
        int row = f >> 4, c4 = (f & 15) << 2;
        float4 v = *(const float4*)(qbase + (size_t)row * E3 + c4);
        float4 vb, vs;
        v.x *= scale; v.y *= scale; v.z *= scale; v.w *= scale;
        vb.x = tf32r(v.x); vs.x = tf32r(v.x - vb.x);
        vb.y = tf32r(v.y); vs.y = tf32r(v.y - vb.y);
        vb.z = tf32r(v.z); vs.z = tf32r(v.z - vb.z);
        vb.w = tf32r(v.w); vs.w = tf32r(v.w - vb.w);
        *(float4*)&Qb[row * AT_STR + c4] = vb;
        *(float4*)&Qs[row * AT_STR + c4] = vs;
    }

    float pacc[8][4] = {};
    float m0r = -3.0e38f, m1r = -3.0e38f;
    float l0 = 0.0f, l1 = 0.0f;

    for (int n = 0; n <= qt; ++n) {
        __syncthreads();   // all PV/S reads of prev K,V done

        // Load K (split) and V (rna, transposed)
        const float* kbase = qkv + (size_t)(b * T_ + n * 64) * E3 + D_ + h * DH_;
        #pragma unroll
        for (int i = 0; i < 8; ++i) {
            int f = tid + i * 128;
            int row = f >> 4, c4 = (f & 15) << 2;
            const float* kp = kbase + (size_t)row * E3 + c4;
            float4 kv = *(const float4*)kp;
            float4 vv = *(const float4*)(kp + D_);
            float4 cb, cs;
            cb.x = tf32r(kv.x); cs.x = tf32r(kv.x - cb.x);
            cb.y = tf32r(kv.y); cs.y = tf32r(kv.y - cb.y);
            cb.z = tf32r(kv.z); cs.z = tf32r(kv.z - cb.z);
            cb.w = tf32r(kv.w); cs.w = tf32r(kv.w - cb.w);
            *(float4*)&Kb[row * AT_STR + c4] = cb;
            *(float4*)&Ks[row * AT_STR + c4] = cs;
            Vt[(c4 + 0) * AT_STR + row] = tf32r(vv.x);
            Vt[(c4 + 1) * AT_STR + row] = tf32r(vv.y);
            Vt[(c4 + 2) * AT_STR + row] = tf32r(vv.z);
            Vt[(c4 + 3) * AT_STR + row] = tf32r(vv.w);
        }
        __syncthreads();

        // S = Q @ K^T  (3x tf32 split: bb + bs + sb)
        float sacc[8][4] = {};
        #pragma unroll
        for (int ks = 0; ks < 64; ks += 8) {
            float ab[4], as_[4];
            int aoff = (m0 + g) * AT_STR + ks + t;
            ab[0]  = Qb[aoff];              ab[1]  = Qb[aoff + 8 * AT_STR];
            ab[2]  = Qb[aoff + 4];          ab[3]  = Qb[aoff + 8 * AT_STR + 4];
            as_[0] = Qs[aoff];              as_[1] = Qs[aoff + 8 * AT_STR];
            as_[2] = Qs[aoff + 4];          as_[3] = Qs[aoff + 8 * AT_STR + 4];
            #pragma unroll
            for (int j = 0; j < 8; ++j) {
                int boff = (j * 8 + g) * AT_STR + ks + t;
                float bb0 = Kb[boff], bb1 = Kb[boff + 4];
                float bs0 = Ks[boff], bs1 = Ks[boff + 4];
                mma_tf32(sacc[j], ab, bb0, bb1);
                mma_tf32(sacc[j], ab, bs0, bs1);
                mma_tf32(sacc[j], as_, bb0, bb1);
            }
        }

        // Causal mask on diagonal tile
        if (n == qt) {
            #pragma unroll
            for (int j = 0; j < 8; ++j) {
                int c0 = j * 8 + 2 * t, c1 = c0 + 1;
                int r0 = m0 + g, r1 = r0 + 8;
                if (c0 > r0) sacc[j][0] = -3.0e38f;
                if (c1 > r0) sacc[j][1] = -3.0e38f;
                if (c0 > r1) sacc[j][2] = -3.0e38f;
                if (c1 > r1) sacc[j][3] = -3.0e38f;
            }
        }

        // Online softmax (register frags, quad shuffles)
        float mx0 = -3.0e38f, mx1 = -3.0e38f;
        #pragma unroll
        for (int j = 0; j < 8; ++j) {
            mx0 = fmaxf(mx0, fmaxf(sacc[j][0], sacc[j][1]));
            mx1 = fmaxf(mx1, fmaxf(sacc[j][2], sacc[j][3]));
        }
        mx0 = fmaxf(mx0, __shfl_xor_sync(0xffffffffu, mx0, 1));
        mx0 = fmaxf(mx0, __shfl_xor_sync(0xffffffffu, mx0, 2));
        mx1 = fmaxf(mx1, __shfl_xor_sync(0xffffffffu, mx1, 1));
        mx1 = fmaxf(mx1, __shfl_xor_sync(0xffffffffu, mx1, 2));

        float mn0 = fmaxf(m0r, mx0);
        float mn1 = fmaxf(m1r, mx1);
        float cr0 = __expf(m0r - mn0);
        float cr1 = __expf(m1r - mn1);
        m0r = mn0; m1r = mn1;

        float rs0 = 0.0f, rs1 = 0.0f;
        #pragma unroll
        for (int j = 0; j < 8; ++j) {
            float p0 = __expf(sacc[j][0] - mn0);
            float p1 = __expf(sacc[j][1] - mn0);
            float p2 = __expf(sacc[j][2] - mn1);
            float p3 = __expf(sacc[j][3] - mn1);
            rs0 += p0 + p1; rs1 += p2 + p3;
            // store rna-rounded P for the PV mma
            int prow0 = (m0 + g) * AT_STR + j * 8 + 2 * t;
            *(float2*)&Ps[prow0]                = make_float2(tf32r(p0), tf32r(p1));
            *(float2*)&Ps[prow0 + 8 * AT_STR]   = make_float2(tf32r(p2), tf32r(p3));
        }
        rs0 += __shfl_xor_sync(0xffffffffu, rs0, 1);
        rs0 += __shfl_xor_sync(0xffffffffu, rs0, 2);
        rs1 += __shfl_xor_sync(0xffffffffu, rs1, 1);
        rs1 += __shfl_xor_sync(0xffffffffu, rs1, 2);
        l0 = l0 * cr0 + rs0;
        l1 = l1 * cr1 + rs1;

        #pragma unroll
        for (int j = 0; j < 8; ++j) {
            pacc[j][0] *= cr0; pacc[j][1] *= cr0;
            pacc[j][2] *= cr1; pacc[j][3] *= cr1;
        }
        __syncwarp();   // P visible within warp (rows are warp-private)

        // O += P @ V
        #pragma unroll
        for (int ks = 0; ks < 64; ks += 8) {
            float pf[4];
            int poff = (m0 + g) * AT_STR + ks + t;
            pf[0] = Ps[poff];     pf[1] = Ps[poff + 8 * AT_STR];
            pf[2] = Ps[poff + 4]; pf[3] = Ps[poff + 8 * AT_STR + 4];
            #pragma unroll
            for (int j = 0; j < 8; ++j) {
                int voff = (j * 8 + g) * AT_STR + ks + t;
                mma_tf32(pacc[j], pf, Vt[voff], Vt[voff + 4]);
            }
        }
    }

    // Epilogue: normalize, rna-round (proj GEMM consumes raw), store
    float linv0 = 1.0f / l0, linv1 = 1.0f / l1;
    float* obase = out + (size_t)(b * T_ + qt * 64) * D_ + h * DH_;
    #pragma unroll
    for (int j = 0; j < 8; ++j) {
        *(float2*)(obase + (size_t)(m0 + g) * D_ + j * 8 + 2 * t) =
            make_float2(tf32r(pacc[j][0] * linv0), tf32r(pacc[j][1] * linv0));
        *(float2*)(obase + (size_t)(m0 + g + 8) * D_ + j * 8 + 2 * t) =
            make_float2(tf32r(pacc[j][2] * linv1), tf32r(pacc[j][3] * linv1));
    }
}

// ---------------------------------------------------------------------------
extern "C" void kernel_launch(void* const* d_in, const int* in_sizes, int n_in,
                              void* d_out, int out_size)
{
    const float* x      = (const float*)d_in[0];
    const float* w_attn = (const float*)d_in[1];
    const float* w_proj = (const float*)d_in[2];
    float* out = (float*)d_out;

    float *qkv, *att, *xr, *war, *wpr;
    cudaGetSymbolAddress((void**)&qkv, g_qkv);
    cudaGetSymbolAddress((void**)&att, g_att);
    cudaGetSymbolAddress((void**)&xr,  g_xr);
    cudaGetSymbolAddress((void**)&war, g_war);
    cudaGetSymbolAddress((void**)&wpr, g_wpr);

    cudaFuncSetAttribute(gemm_nt_tf32,
                         cudaFuncAttributeMaxDynamicSharedMemorySize, GEMM_SMEM_BYTES);
    cudaFuncSetAttribute(attn_mma_kernel,
                         cudaFuncAttributeMaxDynamicSharedMemorySize, ATTN_SMEM_BYTES);

    // 0) Pre-round inputs to tf32 (rna) so GEMMs can cp.async raw
    {
        int n4x = NTOK * D_ / 4, n4a = E3 * D_ / 4, n4p = D_ * D_ / 4;
        round_tf32_kernel<<<(n4x + 255) / 256, 256>>>((const float4*)x, (float4*)xr, n4x);
        round_tf32_kernel<<<(n4a + 255) / 256, 256>>>((const float4*)w_attn, (float4*)war, n4a);
        round_tf32_kernel<<<(n4p + 255) / 256, 256>>>((const float4*)w_proj, (float4*)wpr, n4p);
    }

    // 1) QKV projection
    {
        dim3 grid(E3 / BN, NTOK / BM);
        gemm_nt_tf32<<<grid, 256, GEMM_SMEM_BYTES>>>(xr, war, qkv, NTOK, E3, D_);
    }

    // 2) Causal flash attention (tensor cores)
    {
        dim3 grid(T_ / 64, H_, B_);
        attn_mma_kernel<<<grid, 128, ATTN_SMEM_BYTES>>>(qkv, att);
    }

    // 3) Output projection
    {
        dim3 grid(D_ / BN, NTOK / BM);
        gemm_nt_tf32<<<grid, 256, GEMM_SMEM_BYTES>>>(att, wpr, out, NTOK, D_, D_);
    }
}

// round 4
// speedup vs baseline: 2.6942x; 1.0055x over previous
#include <cuda_runtime.h>
#include <math.h>
#include <stdint.h>

// Problem constants
#define B_   4
#define T_   2048
#define D_   1024
#define H_   16
#define DH_  64
#define NTOK (B_ * T_)     // 8192
#define E3   (3 * D_)      // 3072

// Scratch (device globals: allocation-free rule)
__device__ __align__(16) float g_qkv[NTOK * E3];   // [8192, 3072]
__device__ __align__(16) float g_att[NTOK * D_];   // [8192, 1024]
__device__ __align__(16) float g_xr [NTOK * D_];   // tf32-rounded x
__device__ __align__(16) float g_war[E3 * D_];     // tf32-rounded w_attn
__device__ __align__(16) float g_wpr[D_ * D_];     // tf32-rounded w_proj

// ---------------------------------------------------------------------------
// Helpers
// ---------------------------------------------------------------------------
__device__ __forceinline__ float tf32r(float x) {
    uint32_t u;
    asm("cvt.rna.tf32.f32 %0, %1;" : "=r"(u) : "f"(x));
    return __uint_as_float(u);
}

__device__ __forceinline__ void mma_tf32(float* c, const float* a, float b0, float b1) {
    asm volatile(
        "mma.sync.aligned.m16n8k8.row.col.f32.tf32.tf32.f32 "
        "{%0,%1,%2,%3}, {%4,%5,%6,%7}, {%8,%9}, {%0,%1,%2,%3};\n"
        : "+f"(c[0]), "+f"(c[1]), "+f"(c[2]), "+f"(c[3])
        : "r"(__float_as_uint(a[0])), "r"(__float_as_uint(a[1])),
          "r"(__float_as_uint(a[2])), "r"(__float_as_uint(a[3])),
          "r"(__float_as_uint(b0)), "r"(__float_as_uint(b1)));
}

__device__ __forceinline__ void cp_async16(void* smem_dst, const void* gsrc) {
    uint32_t s = (uint32_t)__cvta_generic_to_shared(smem_dst);
    asm volatile("cp.async.cg.shared.global [%0], [%1], 16;\n" :: "r"(s), "l"(gsrc) : "memory");
}
__device__ __forceinline__ void cp_commit() {
    asm volatile("cp.async.commit_group;\n" ::: "memory");
}
template<int N>
__device__ __forceinline__ void cp_wait() {
    asm volatile("cp.async.wait_group %0;\n" :: "n"(N) : "memory");
}

// ---------------------------------------------------------------------------
// Pre-round to tf32 (rna), elementwise
// ---------------------------------------------------------------------------
__global__ void round_tf32_kernel(const float4* __restrict__ in,
                                  float4* __restrict__ out, int n4)
{
    int i = blockIdx.x * blockDim.x + threadIdx.x;
    if (i < n4) {
        float4 v = in[i];
        v.x = tf32r(v.x); v.y = tf32r(v.y); v.z = tf32r(v.z); v.w = tf32r(v.w);
        out[i] = v;
    }
}

// ---------------------------------------------------------------------------
// TF32 NT GEMM, inputs pre-rounded to tf32. BM=BN=128, BK=16, 3-stage cp.async.
// 256 threads (8 warps), warp tile 64x32.
// ---------------------------------------------------------------------------
#define BM 128
#define BN 128
#define BK 16
#define TSTR 20
#define GEMM_STAGE_WORDS (BM * TSTR)         // 2560 words per tile
#define GEMM_SMEM_BYTES (3 * 2 * GEMM_STAGE_WORDS * 4)  // 61440

__global__ void __launch_bounds__(256, 2)
gemm_nt_tf32(const float* __restrict__ A, const float* __restrict__ Bm,
             float* __restrict__ C, int M, int N, int K)
{
    extern __shared__ float smg[];
    // stage s: A at smg + s*2*SW, B at + SW
    const int SW = GEMM_STAGE_WORDS;

    const int tid  = threadIdx.x;
    const int lane = tid & 31;
    const int warp = tid >> 5;
    const int wm   = (warp >> 2) * 64;
    const int wn   = (warp & 3) * 32;
    const int m0   = blockIdx.y * BM;
    const int n0   = blockIdx.x * BN;

    float acc[4][4][4] = {};

    const int nIter = K / BK;

    auto issue = [&](int it, int s) {
        float* As = smg + s * 2 * SW;
        float* Bs = As + SW;
        int k0 = it * BK;
        #pragma unroll
        for (int i = 0; i < 2; ++i) {
            int c   = tid + i * 256;
            int row = c >> 2;
            int lk  = (c & 3) << 2;
            cp_async16(&As[row * TSTR + lk], &A[(size_t)(m0 + row) * K + k0 + lk]);
            cp_async16(&Bs[row * TSTR + lk], &Bm[(size_t)(n0 + row) * K + k0 + lk]);
        }
        cp_commit();
    };

    issue(0, 0);
    issue(1, 1);

    for (int it = 0; it < nIter; ++it) {
        int s = it % 3;
        cp_wait<1>();
        __syncthreads();
        if (it + 2 < nIter) issue(it + 2, (it + 2) % 3);
        else cp_commit();   // keep group accounting uniform

        const float* As = smg + s * 2 * SW;
        const float* Bs = As + SW;

        #pragma unroll
        for (int ks = 0; ks < BK; ks += 8) {
            float af[4][4], bf[4][2];
            const int kk = ks + (lane & 3);
            #pragma unroll
            for (int mi = 0; mi < 4; ++mi) {
                int row = wm + mi * 16 + (lane >> 2);
                af[mi][0] = As[row * TSTR + kk];
                af[mi][1] = As[(row + 8) * TSTR + kk];
                af[mi][2] = As[row * TSTR + kk + 4];
                af[mi][3] = As[(row + 8) * TSTR + kk + 4];
            }
            #pragma unroll
            for (int nj = 0; nj < 4; ++nj) {
                int col = wn + nj * 8 + (lane >> 2);
                bf[nj][0] = Bs[col * TSTR + kk];
                bf[nj][1] = Bs[col * TSTR + kk + 4];
            }
            #pragma unroll
            for (int mi = 0; mi < 4; ++mi)
                #pragma unroll
                for (int nj = 0; nj < 4; ++nj)
                    mma_tf32(acc[mi][nj], af[mi], bf[nj][0], bf[nj][1]);
        }
        __syncthreads();
    }

    #pragma unroll
    for (int mi = 0; mi < 4; ++mi) {
        int row = m0 + wm + mi * 16 + (lane >> 2);
        #pragma unroll
        for (int nj = 0; nj < 4; ++nj) {
            int col = n0 + wn + nj * 8 + ((lane & 3) << 1);
            *(float2*)&C[(size_t)row * N + col] =
                make_float2(acc[mi][nj][0], acc[mi][nj][1]);
            *(float2*)&C[(size_t)(row + 8) * N + col] =
                make_float2(acc[mi][nj][2], acc[mi][nj][3]);
        }
    }
}

// ---------------------------------------------------------------------------
// Flash attention on tensor cores (tf32 mma, 3x-split for S, fp32 softmax).
// BLOCK_M=64 q rows, key tiles of 64, DH=64. 128 threads (4 warps),
// each warp owns 16 q rows. S-frags + O-acc in registers.
// ---------------------------------------------------------------------------
#define AT_STR 68
#define ATTN_SMEM_BYTES (6 * 64 * AT_STR * 4)   // 104448

__global__ void __launch_bounds__(128, 2)
attn_mma_kernel(const float* __restrict__ qkv, float* __restrict__ out)
{
    extern __shared__ float sm[];
    float* Qb = sm;                  // [row][d]  big
    float* Qs = Qb + 64 * AT_STR;    // [row][d]  small
    float* Kb = Qs + 64 * AT_STR;    // [key][d]  big
    float* Ks = Kb + 64 * AT_STR;    // [key][d]  small
    float* Vt = Ks + 64 * AT_STR;    // [d][key]  (rna)
    float* Ps = Vt + 64 * AT_STR;    // [row][key] (rna)

    const int tid  = threadIdx.x;
    const int lane = tid & 31;
    const int warp = tid >> 5;
    const int g    = lane >> 2;      // 0..7
    const int t    = lane & 3;       // 0..3
    const int m0   = warp * 16;
    const int qt   = gridDim.x - 1 - blockIdx.x;   // big tiles first
    const int h    = blockIdx.y;
    const int b    = blockIdx.z;

    const float scale = 0.125f;
    const float* qbase = qkv + (size_t)(b * T_ + qt * 64) * E3 + h * DH_;

    // Load Q, pre-scale, split big/small
    #pragma unroll
    for (int i = 0; i < 8; ++i) {
        int f = tid + i * 128;
        int row = f >> 4, c4 = (f & 15) << 2;
        float4 v = *(const float4*)(qbase + (size_t)row * E3 + c4);
        float4 vb, vs;
        v.x *= scale; v.y *= scale; v.z *= scale; v.w *= scale;
        vb.x = tf32r(v.x); vs.x = tf32r(v.x - vb.x);
        vb.y = tf32r(v.y); vs.y = tf32r(v.y - vb.y);
        vb.z = tf32r(v.z); vs.z = tf32r(v.z - vb.z);
        vb.w = tf32r(v.w); vs.w = tf32r(v.w - vb.w);
        *(float4*)&Qb[row * AT_STR + c4] = vb;
        *(float4*)&Qs[row * AT_STR + c4] = vs;
    }

    float pacc[8][4] = {};
    float m0r = -3.0e38f, m1r = -3.0e38f;
    float l0 = 0.0f, l1 = 0.0f;

    for (int n = 0; n <= qt; ++n) {
        __syncthreads();   // all PV/S reads of prev K,V done

        // Load K (split) and V (rna, transposed)
        const float* kbase = qkv + (size_t)(b * T_ + n * 64) * E3 + D_ + h * DH_;
        #pragma unroll
        for (int i = 0; i < 8; ++i) {
            int f = tid + i * 128;
            int row = f >> 4, c4 = (f & 15) << 2;
            const float* kp = kbase + (size_t)row * E3 + c4;
            float4 kv = *(const float4*)kp;
            float4 vv = *(const float4*)(kp + D_);
            float4 cb, cs;
            cb.x = tf32r(kv.x); cs.x = tf32r(kv.x - cb.x);
            cb.y = tf32r(kv.y); cs.y = tf32r(kv.y - cb.y);
            cb.z = tf32r(kv.z); cs.z = tf32r(kv.z - cb.z);
            cb.w = tf32r(kv.w); cs.w = tf32r(kv.w - cb.w);
            *(float4*)&Kb[row * AT_STR + c4] = cb;
            *(float4*)&Ks[row * AT_STR + c4] = cs;
            Vt[(c4 + 0) * AT_STR + row] = tf32r(vv.x);
            Vt[(c4 + 1) * AT_STR + row] = tf32r(vv.y);
            Vt[(c4 + 2) * AT_STR + row] = tf32r(vv.z);
            Vt[(c4 + 3) * AT_STR + row] = tf32r(vv.w);
        }
        __syncthreads();

        // S = Q @ K^T  (3x tf32 split: bb + bs + sb)
        float sacc[8][4] = {};
        #pragma unroll
        for (int ks = 0; ks < 64; ks += 8) {
            float ab[4], as_[4];
            int aoff = (m0 + g) * AT_STR + ks + t;
            ab[0]  = Qb[aoff];              ab[1]  = Qb[aoff + 8 * AT_STR];
            ab[2]  = Qb[aoff + 4];          ab[3]  = Qb[aoff + 8 * AT_STR + 4];
            as_[0] = Qs[aoff];              as_[1] = Qs[aoff + 8 * AT_STR];
            as_[2] = Qs[aoff + 4];          as_[3] = Qs[aoff + 8 * AT_STR + 4];
            #pragma unroll
            for (int j = 0; j < 8; ++j) {
                int boff = (j * 8 + g) * AT_STR + ks + t;
                float bb0 = Kb[boff], bb1 = Kb[boff + 4];
                float bs0 = Ks[boff], bs1 = Ks[boff + 4];
                mma_tf32(sacc[j], ab, bb0, bb1);
                mma_tf32(sacc[j], ab, bs0, bs1);
                mma_tf32(sacc[j], as_, bb0, bb1);
            }
        }

        // Causal mask on diagonal tile
        if (n == qt) {
            #pragma unroll
            for (int j = 0; j < 8; ++j) {
                int c0 = j * 8 + 2 * t, c1 = c0 + 1;
                int r0 = m0 + g, r1 = r0 + 8;
                if (c0 > r0) sacc[j][0] = -3.0e38f;
                if (c1 > r0) sacc[j][1] = -3.0e38f;
                if (c0 > r1) sacc[j][2] = -3.0e38f;
                if (c1 > r1) sacc[j][3] = -3.0e38f;
            }
        }

        // Online softmax (register frags, quad shuffles)
        float mx0 = -3.0e38f, mx1 = -3.0e38f;
        #pragma unroll
        for (int j = 0; j < 8; ++j) {
            mx0 = fmaxf(mx0, fmaxf(sacc[j][0], sacc[j][1]));
            mx1 = fmaxf(mx1, fmaxf(sacc[j][2], sacc[j][3]));
        }
        mx0 = fmaxf(mx0, __shfl_xor_sync(0xffffffffu, mx0, 1));
        mx0 = fmaxf(mx0, __shfl_xor_sync(0xffffffffu, mx0, 2));
        mx1 = fmaxf(mx1, __shfl_xor_sync(0xffffffffu, mx1, 1));
        mx1 = fmaxf(mx1, __shfl_xor_sync(0xffffffffu, mx1, 2));

        float mn0 = fmaxf(m0r, mx0);
        float mn1 = fmaxf(m1r, mx1);
        float cr0 = __expf(m0r - mn0);
        float cr1 = __expf(m1r - mn1);
        m0r = mn0; m1r = mn1;

        float rs0 = 0.0f, rs1 = 0.0f;
        #pragma unroll
        for (int j = 0; j < 8; ++j) {
            float p0 = __expf(sacc[j][0] - mn0);
            float p1 = __expf(sacc[j][1] - mn0);
            float p2 = __expf(sacc[j][2] - mn1);
            float p3 = __expf(sacc[j][3] - mn1);
            rs0 += p0 + p1; rs1 += p2 + p3;
            // store rna-rounded P for the PV mma
            int prow0 = (m0 + g) * AT_STR + j * 8 + 2 * t;
            *(float2*)&Ps[prow0]                = make_float2(tf32r(p0), tf32r(p1));
            *(float2*)&Ps[prow0 + 8 * AT_STR]   = make_float2(tf32r(p2), tf32r(p3));
        }
        rs0 += __shfl_xor_sync(0xffffffffu, rs0, 1);
        rs0 += __shfl_xor_sync(0xffffffffu, rs0, 2);
        rs1 += __shfl_xor_sync(0xffffffffu, rs1, 1);
        rs1 += __shfl_xor_sync(0xffffffffu, rs1, 2);
        l0 = l0 * cr0 + rs0;
        l1 = l1 * cr1 + rs1;

        #pragma unroll
        for (int j = 0; j < 8; ++j) {
            pacc[j][0] *= cr0; pacc[j][1] *= cr0;
            pacc[j][2] *= cr1; pacc[j][3] *= cr1;
        }
        __syncwarp();   // P visible within warp (rows are warp-private)

        // O += P @ V
        #pragma unroll
        for (int ks = 0; ks < 64; ks += 8) {
            float pf[4];
            int poff = (m0 + g) * AT_STR + ks + t;
            pf[0] = Ps[poff];     pf[1] = Ps[poff + 8 * AT_STR];
            pf[2] = Ps[poff + 4]; pf[3] = Ps[poff + 8 * AT_STR + 4];
            #pragma unroll
            for (int j = 0; j < 8; ++j) {
                int voff = (j * 8 + g) * AT_STR + ks + t;
                mma_tf32(pacc[j], pf, Vt[voff], Vt[voff + 4]);
            }
        }
    }

    // Epilogue: normalize, rna-round (proj GEMM consumes raw), store
    float linv0 = 1.0f / l0, linv1 = 1.0f / l1;
    float* obase = out + (size_t)(b * T_ + qt * 64) * D_ + h * DH_;
    #pragma unroll
    for (int j = 0; j < 8; ++j) {
        *(float2*)(obase + (size_t)(m0 + g) * D_ + j * 8 + 2 * t) =
            make_float2(tf32r(pacc[j][0] * linv0), tf32r(pacc[j][1] * linv0));
        *(float2*)(obase + (size_t)(m0 + g + 8) * D_ + j * 8 + 2 * t) =
            make_float2(tf32r(pacc[j][2] * linv1), tf32r(pacc[j][3] * linv1));
    }
}

// ---------------------------------------------------------------------------
extern "C" void kernel_launch(void* const* d_in, const int* in_sizes, int n_in,
                              void* d_out, int out_size)
{
    const float* x      = (const float*)d_in[0];
    const float* w_attn = (const float*)d_in[1];
    const float* w_proj = (const float*)d_in[2];
    float* out = (float*)d_out;

    float *qkv, *att, *xr, *war, *wpr;
    cudaGetSymbolAddress((void**)&qkv, g_qkv);
    cudaGetSymbolAddress((void**)&att, g_att);
    cudaGetSymbolAddress((void**)&xr,  g_xr);
    cudaGetSymbolAddress((void**)&war, g_war);
    cudaGetSymbolAddress((void**)&wpr, g_wpr);

    cudaFuncSetAttribute(gemm_nt_tf32,
                         cudaFuncAttributeMaxDynamicSharedMemorySize, GEMM_SMEM_BYTES);
    cudaFuncSetAttribute(attn_mma_kernel,
                         cudaFuncAttributeMaxDynamicSharedMemorySize, ATTN_SMEM_BYTES);

    // 0) Pre-round inputs to tf32 (rna) so GEMMs can cp.async raw
    {
        int n4x = NTOK * D_ / 4, n4a = E3 * D_ / 4, n4p = D_ * D_ / 4;
        round_tf32_kernel<<<(n4x + 255) / 256, 256>>>((const float4*)x, (float4*)xr, n4x);
        round_tf32_kernel<<<(n4a + 255) / 256, 256>>>((const float4*)w_attn, (float4*)war, n4a);
        round_tf32_kernel<<<(n4p + 255) / 256, 256>>>((const float4*)w_proj, (float4*)wpr, n4p);
    }

    // 1) QKV projection
    {
        dim3 grid(E3 / BN, NTOK / BM);
        gemm_nt_tf32<<<grid, 256, GEMM_SMEM_BYTES>>>(xr, war, qkv, NTOK, E3, D_);
    }

    // 2) Causal flash attention (tensor cores)
    {
        dim3 grid(T_ / 64, H_, B_);
        attn_mma_kernel<<<grid, 128, ATTN_SMEM_BYTES>>>(qkv, att);
    }

    // 3) Output projection
    {
        dim3 grid(D_ / BN, NTOK / BM);
        gemm_nt_tf32<<<grid, 256, GEMM_SMEM_BYTES>>>(att, wpr, out, NTOK, D_, D_);
    }
}

// round 6
// speedup vs baseline: 3.1594x; 1.1727x over previous
#include <cuda_runtime.h>
#include <math.h>
#include <stdint.h>

// Problem constants
#define B_   4
#define T_   2048
#define D_   1024
#define H_   16
#define DH_  64
#define NTOK (B_ * T_)     // 8192
#define E3   (3 * D_)      // 3072

// Scratch (device globals: allocation-free rule)
__device__ __align__(16) float g_qkv[NTOK * E3];   // [8192, 3072]
__device__ __align__(16) float g_att[NTOK * D_];   // [8192, 1024]
__device__ __align__(16) float g_xr [NTOK * D_];   // tf32-rounded x
__device__ __align__(16) float g_war[E3 * D_];     // tf32-rounded w_attn
__device__ __align__(16) float g_wpr[D_ * D_];     // tf32-rounded w_proj

// ---------------------------------------------------------------------------
// Helpers
// ---------------------------------------------------------------------------
__device__ __forceinline__ float tf32r(float x) {
    uint32_t u;
    asm("cvt.rna.tf32.f32 %0, %1;" : "=r"(u) : "f"(x));
    return __uint_as_float(u);
}

__device__ __forceinline__ void mma_tf32(float* c, const float* a, float b0, float b1) {
    asm volatile(
        "mma.sync.aligned.m16n8k8.row.col.f32.tf32.tf32.f32 "
        "{%0,%1,%2,%3}, {%4,%5,%6,%7}, {%8,%9}, {%0,%1,%2,%3};\n"
        : "+f"(c[0]), "+f"(c[1]), "+f"(c[2]), "+f"(c[3])
        : "r"(__float_as_uint(a[0])), "r"(__float_as_uint(a[1])),
          "r"(__float_as_uint(a[2])), "r"(__float_as_uint(a[3])),
          "r"(__float_as_uint(b0)), "r"(__float_as_uint(b1)));
}

__device__ __forceinline__ void cp_async16(void* smem_dst, const void* gsrc) {
    uint32_t s = (uint32_t)__cvta_generic_to_shared(smem_dst);
    asm volatile("cp.async.cg.shared.global [%0], [%1], 16;\n" :: "r"(s), "l"(gsrc) : "memory");
}
__device__ __forceinline__ void cp_commit() {
    asm volatile("cp.async.commit_group;\n" ::: "memory");
}
template<int N>
__device__ __forceinline__ void cp_wait() {
    asm volatile("cp.async.wait_group %0;\n" :: "n"(N) : "memory");
}

// ---------------------------------------------------------------------------
// Pre-round to tf32 (rna), elementwise
// ---------------------------------------------------------------------------
__global__ void round_tf32_kernel(const float4* __restrict__ in,
                                  float4* __restrict__ out, int n4)
{
    int i = blockIdx.x * blockDim.x + threadIdx.x;
    if (i < n4) {
        float4 v = in[i];
        v.x = tf32r(v.x); v.y = tf32r(v.y); v.z = tf32r(v.z); v.w = tf32r(v.w);
        out[i] = v;
    }
}

// ---------------------------------------------------------------------------
// TF32 NT GEMM, inputs pre-rounded. BM=BN=128, BK=32, 2-stage cp.async
// double buffer. 256 threads (8 warps), warp tile 64x32 via mma.m16n8k8.
// ---------------------------------------------------------------------------
#define BM 128
#define BN 128
#define BK 32
#define TSTR 36                                   // 32 + 4 pad words
#define GEMM_STAGE_WORDS (BM * TSTR)              // 4608 words per tile
#define GEMM_SMEM_BYTES (2 * 2 * GEMM_STAGE_WORDS * 4)   // 73728

__global__ void __launch_bounds__(256, 2)
gemm_nt_tf32(const float* __restrict__ A, const float* __restrict__ Bm,
             float* __restrict__ C, int M, int N, int K)
{
    extern __shared__ float smg[];
    const int SW = GEMM_STAGE_WORDS;

    const int tid  = threadIdx.x;
    const int lane = tid & 31;
    const int warp = tid >> 5;
    const int wm   = (warp >> 2) * 64;
    const int wn   = (warp & 3) * 32;
    const int m0   = blockIdx.y * BM;
    const int n0   = blockIdx.x * BN;

    float acc[4][4][4] = {};

    const int nIter = K / BK;   // 32

    auto issue = [&](int it, int s) {
        float* As = smg + s * 2 * SW;
        float* Bs = As + SW;
        int k0 = it * BK;
        #pragma unroll
        for (int i = 0; i < 4; ++i) {
            int c   = tid + i * 256;          // 0..1023 float4 chunks
            int row = c >> 3;                 // 8 float4 per row (32 floats)
            int lk  = (c & 7) << 2;
            cp_async16(&As[row * TSTR + lk], &A[(size_t)(m0 + row) * K + k0 + lk]);
            cp_async16(&Bs[row * TSTR + lk], &Bm[(size_t)(n0 + row) * K + k0 + lk]);
        }
        cp_commit();
    };

    issue(0, 0);
    issue(1, 1);

    for (int it = 0; it < nIter; ++it) {
        int s = it & 1;
        cp_wait<1>();
        __syncthreads();

        const float* As = smg + s * 2 * SW;
        const float* Bs = As + SW;

        #pragma unroll
        for (int ks = 0; ks < BK; ks += 8) {
            float af[4][4], bf[4][2];
            const int kk = ks + (lane & 3);
            #pragma unroll
            for (int mi = 0; mi < 4; ++mi) {
                int row = wm + mi * 16 + (lane >> 2);
                af[mi][0] = As[row * TSTR + kk];
                af[mi][1] = As[(row + 8) * TSTR + kk];
                af[mi][2] = As[row * TSTR + kk + 4];
                af[mi][3] = As[(row + 8) * TSTR + kk + 4];
            }
            #pragma unroll
            for (int nj = 0; nj < 4; ++nj) {
                int col = wn + nj * 8 + (lane >> 2);
                bf[nj][0] = Bs[col * TSTR + kk];
                bf[nj][1] = Bs[col * TSTR + kk + 4];
            }
            #pragma unroll
            for (int mi = 0; mi < 4; ++mi)
                #pragma unroll
                for (int nj = 0; nj < 4; ++nj)
                    mma_tf32(acc[mi][nj], af[mi], bf[nj][0], bf[nj][1]);
        }
        __syncthreads();
        if (it + 2 < nIter) issue(it + 2, s);
        else cp_commit();   // keep group accounting uniform
    }

    #pragma unroll
    for (int mi = 0; mi < 4; ++mi) {
        int row = m0 + wm + mi * 16 + (lane >> 2);
        #pragma unroll
        for (int nj = 0; nj < 4; ++nj) {
            int col = n0 + wn + nj * 8 + ((lane & 3) << 1);
            *(float2*)&C[(size_t)row * N + col] =
                make_float2(acc[mi][nj][0], acc[mi][nj][1]);
            *(float2*)&C[(size_t)(row + 8) * N + col] =
                make_float2(acc[mi][nj][2], acc[mi][nj][3]);
        }
    }
}

// ---------------------------------------------------------------------------
// Flash attention on tensor cores (single tf32 mma for S, fp32 softmax).
// BLOCK_M=64 q rows, key tiles of 64, DH=64. 128 threads (4 warps),
// each warp owns 16 q rows. S-frags + O-acc in registers.
// ---------------------------------------------------------------------------
#define AT_STR 68
#define ATTN_SMEM_BYTES (4 * 64 * AT_STR * 4)   // 69632

__global__ void __launch_bounds__(128, 3)
attn_mma_kernel(const float* __restrict__ qkv, float* __restrict__ out)
{
    extern __shared__ float sm[];
    float* Qb = sm;                  // [row][d]   q, scaled + rna
    float* Kb = Qb + 64 * AT_STR;    // [key][d]   rna
    float* Vt = Kb + 64 * AT_STR;    // [d][key]   rna
    float* Ps = Vt + 64 * AT_STR;    // [row][key] rna

    const int tid  = threadIdx.x;
    const int lane = tid & 31;
    const int warp = tid >> 5;
    const int g    = lane >> 2;      // 0..7
    const int t    = lane & 3;       // 0..3
    const int m0   = warp * 16;
    const int qt   = gridDim.x - 1 - blockIdx.x;   // big tiles first
    const int h    = blockIdx.y;
    const int b    = blockIdx.z;

    const float scale = 0.125f;
    const float* qbase = qkv + (size_t)(b * T_ + qt * 64) * E3 + h * DH_;

    // Load Q, pre-scale, round to tf32
    #pragma unroll
    for (int i = 0; i < 8; ++i) {
        int f = tid + i * 128;
        int row = f >> 4, c4 = (f & 15) << 2;
        float4 v = *(const float4*)(qbase + (size_t)row * E3 + c4);
        v.x = tf32r(v.x * scale); v.y = tf32r(v.y * scale);
        v.z = tf32r(v.z * scale); v.w = tf32r(v.w * scale);
        *(float4*)&Qb[row * AT_STR + c4] = v;
    }

    float pacc[8][4] = {};
    float m0r = -3.0e38f, m1r = -3.0e38f;
    float l0 = 0.0f, l1 = 0.0f;

    for (int n = 0; n <= qt; ++n) {
        __syncthreads();   // all PV/S reads of prev K,V done

        // Load K (rna) and V (rna, transposed)
        const float* kbase = qkv + (size_t)(b * T_ + n * 64) * E3 + D_ + h * DH_;
        #pragma unroll
        for (int i = 0; i < 8; ++i) {
            int f = tid + i * 128;
            int row = f >> 4, c4 = (f & 15) << 2;
            const float* kp = kbase + (size_t)row * E3 + c4;
            float4 kv = *(const float4*)kp;
            float4 vv = *(const float4*)(kp + D_);
            kv.x = tf32r(kv.x); kv.y = tf32r(kv.y);
            kv.z = tf32r(kv.z); kv.w = tf32r(kv.w);
            *(float4*)&Kb[row * AT_STR + c4] = kv;
            Vt[(c4 + 0) * AT_STR + row] = tf32r(vv.x);
            Vt[(c4 + 1) * AT_STR + row] = tf32r(vv.y);
            Vt[(c4 + 2) * AT_STR + row] = tf32r(vv.z);
            Vt[(c4 + 3) * AT_STR + row] = tf32r(vv.w);
        }
        __syncthreads();

        // S = Q @ K^T
        float sacc[8][4] = {};
        #pragma unroll
        for (int ks = 0; ks < 64; ks += 8) {
            float ab[4];
            int aoff = (m0 + g) * AT_STR + ks + t;
            ab[0] = Qb[aoff];     ab[1] = Qb[aoff + 8 * AT_STR];
            ab[2] = Qb[aoff + 4]; ab[3] = Qb[aoff + 8 * AT_STR + 4];
            #pragma unroll
            for (int j = 0; j < 8; ++j) {
                int boff = (j * 8 + g) * AT_STR + ks + t;
                mma_tf32(sacc[j], ab, Kb[boff], Kb[boff + 4]);
            }
        }

        // Causal mask on diagonal tile
        if (n == qt) {
            #pragma unroll
            for (int j = 0; j < 8; ++j) {
                int c0 = j * 8 + 2 * t, c1 = c0 + 1;
                int r0 = m0 + g, r1 = r0 + 8;
                if (c0 > r0) sacc[j][0] = -3.0e38f;
                if (c1 > r0) sacc[j][1] = -3.0e38f;
                if (c0 > r1) sacc[j][2] = -3.0e38f;
                if (c1 > r1) sacc[j][3] = -3.0e38f;
            }
        }

        // Online softmax (register frags, quad shuffles)
        float mx0 = -3.0e38f, mx1 = -3.0e38f;
        #pragma unroll
        for (int j = 0; j < 8; ++j) {
            mx0 = fmaxf(mx0, fmaxf(sacc[j][0], sacc[j][1]));
            mx1 = fmaxf(mx1, fmaxf(sacc[j][2], sacc[j][3]));
        }
        mx0 = fmaxf(mx0, __shfl_xor_sync(0xffffffffu, mx0, 1));
        mx0 = fmaxf(mx0, __shfl_xor_sync(0xffffffffu, mx0, 2));
        mx1 = fmaxf(mx1, __shfl_xor_sync(0xffffffffu, mx1, 1));
        mx1 = fmaxf(mx1, __shfl_xor_sync(0xffffffffu, mx1, 2));

        float mn0 = fmaxf(m0r, mx0);
        float mn1 = fmaxf(m1r, mx1);
        float cr0 = __expf(m0r - mn0);
        float cr1 = __expf(m1r - mn1);
        m0r = mn0; m1r = mn1;

        float rs0 = 0.0f, rs1 = 0.0f;
        #pragma unroll
        for (int j = 0; j < 8; ++j) {
            float p0 = __expf(sacc[j][0] - mn0);
            float p1 = __expf(sacc[j][1] - mn0);
            float p2 = __expf(sacc[j][2] - mn1);
            float p3 = __expf(sacc[j][3] - mn1);
            rs0 += p0 + p1; rs1 += p2 + p3;
            int prow0 = (m0 + g) * AT_STR + j * 8 + 2 * t;
            *(float2*)&Ps[prow0]              = make_float2(tf32r(p0), tf32r(p1));
            *(float2*)&Ps[prow0 + 8 * AT_STR] = make_float2(tf32r(p2), tf32r(p3));
        }
        rs0 += __shfl_xor_sync(0xffffffffu, rs0, 1);
        rs0 += __shfl_xor_sync(0xffffffffu, rs0, 2);
        rs1 += __shfl_xor_sync(0xffffffffu, rs1, 1);
        rs1 += __shfl_xor_sync(0xffffffffu, rs1, 2);
        l0 = l0 * cr0 + rs0;
        l1 = l1 * cr1 + rs1;

        #pragma unroll
        for (int j = 0; j < 8; ++j) {
            pacc[j][0] *= cr0; pacc[j][1] *= cr0;
            pacc[j][2] *= cr1; pacc[j][3] *= cr1;
        }
        __syncwarp();   // P visible within warp (rows are warp-private)

        // O += P @ V
        #pragma unroll
        for (int ks = 0; ks < 64; ks += 8) {
            float pf[4];
            int poff = (m0 + g) * AT_STR + ks + t;
            pf[0] = Ps[poff];     pf[1] = Ps[poff + 8 * AT_STR];
            pf[2] = Ps[poff + 4]; pf[3] = Ps[poff + 8 * AT_STR + 4];
            #pragma unroll
            for (int j = 0; j < 8; ++j) {
                int voff = (j * 8 + g) * AT_STR + ks + t;
                mma_tf32(pacc[j], pf, Vt[voff], Vt[voff + 4]);
            }
        }
    }

    // Epilogue: normalize, rna-round (proj GEMM consumes raw), store
    float linv0 = 1.0f / l0, linv1 = 1.0f / l1;
    float* obase = out + (size_t)(b * T_ + qt * 64) * D_ + h * DH_;
    #pragma unroll
    for (int j = 0; j < 8; ++j) {
        *(float2*)(obase + (size_t)(m0 + g) * D_ + j * 8 + 2 * t) =
            make_float2(tf32r(pacc[j][0] * linv0), tf32r(pacc[j][1] * linv0));
        *(float2*)(obase + (size_t)(m0 + g + 8) * D_ + j * 8 + 2 * t) =
            make_float2(tf32r(pacc[j][2] * linv1), tf32r(pacc[j][3] * linv1));
    }
}

// ---------------------------------------------------------------------------
extern "C" void kernel_launch(void* const* d_in, const int* in_sizes, int n_in,
                              void* d_out, int out_size)
{
    const float* x      = (const float*)d_in[0];
    const float* w_attn = (const float*)d_in[1];
    const float* w_proj = (const float*)d_in[2];
    float* out = (float*)d_out;

    float *qkv, *att, *xr, *war, *wpr;
    cudaGetSymbolAddress((void**)&qkv, g_qkv);
    cudaGetSymbolAddress((void**)&att, g_att);
    cudaGetSymbolAddress((void**)&xr,  g_xr);
    cudaGetSymbolAddress((void**)&war, g_war);
    cudaGetSymbolAddress((void**)&wpr, g_wpr);

    cudaFuncSetAttribute(gemm_nt_tf32,
                         cudaFuncAttributeMaxDynamicSharedMemorySize, GEMM_SMEM_BYTES);
    cudaFuncSetAttribute(attn_mma_kernel,
                         cudaFuncAttributeMaxDynamicSharedMemorySize, ATTN_SMEM_BYTES);

    // 0) Pre-round inputs to tf32 (rna) so GEMMs can cp.async raw
    {
        int n4x = NTOK * D_ / 4, n4a = E3 * D_ / 4, n4p = D_ * D_ / 4;
        round_tf32_kernel<<<(n4x + 255) / 256, 256>>>((const float4*)x, (float4*)xr, n4x);
        round_tf32_kernel<<<(n4a + 255) / 256, 256>>>((const float4*)w_attn, (float4*)war, n4a);
        round_tf32_kernel<<<(n4p + 255) / 256, 256>>>((const float4*)w_proj, (float4*)wpr, n4p);
    }

    // 1) QKV projection
    {
        dim3 grid(E3 / BN, NTOK / BM);
        gemm_nt_tf32<<<grid, 256, GEMM_SMEM_BYTES>>>(xr, war, qkv, NTOK, E3, D_);
    }

    // 2) Causal flash attention (tensor cores)
    {
        dim3 grid(T_ / 64, H_, B_);
        attn_mma_kernel<<<grid, 128, ATTN_SMEM_BYTES>>>(qkv, att);
    }

    // 3) Output projection
    {
        dim3 grid(D_ / BN, NTOK / BM);
        gemm_nt_tf32<<<grid, 256, GEMM_SMEM_BYTES>>>(att, wpr, out, NTOK, D_, D_);
    }
}